// round 1
// baseline (speedup 1.0000x reference)
#include <cuda_runtime.h>
#include <math.h>

// Problem constants
#define B_   2
#define S_   2048
#define D_   2048
#define H_   16
#define HD_  128
#define M_   (B_ * S_)      // 4096 rows of x
#define NQKV (3 * D_)       // 6144

// ---------------- scratch (device globals; no allocation allowed) ----------
__device__ float g_qkv[(size_t)M_ * NQKV];            // 96 MB
__device__ float g_q  [(size_t)B_ * H_ * S_ * HD_];   // 32 MB  [b,h,s,hd]
__device__ float g_k  [(size_t)B_ * H_ * S_ * HD_];
__device__ float g_v  [(size_t)B_ * H_ * S_ * HD_];
__device__ float g_attn[(size_t)M_ * D_];             // [b,s,h,hd] -> [M, D]

// ---------------------------------------------------------------------------
// SGEMM NT: C[M,N] = A[M,K] * B[N,K]^T   (both row-major, K contiguous)
// 128x128 tile, BK=8, 256 threads, 8x8 microtile.
// ---------------------------------------------------------------------------
__global__ __launch_bounds__(256)
void sgemm_nt(const float* __restrict__ A, const float* __restrict__ B,
              float* __restrict__ C, int M, int N, int K)
{
    __shared__ float As[8][128];
    __shared__ float Bs[8][128];

    const int t  = threadIdx.x;
    const int tx = t & 15;
    const int ty = t >> 4;
    const int rowBase = blockIdx.y << 7;
    const int colBase = blockIdx.x << 7;

    const int lr = t >> 1;          // 0..127
    const int lc = (t & 1) << 2;    // 0 or 4
    const float* Ap = A + (size_t)(rowBase + lr) * K + lc;
    const float* Bp = B + (size_t)(colBase + lr) * K + lc;

    float acc[8][8];
#pragma unroll
    for (int i = 0; i < 8; ++i)
#pragma unroll
        for (int j = 0; j < 8; ++j) acc[i][j] = 0.f;

    for (int k0 = 0; k0 < K; k0 += 8) {
        float4 av = *(const float4*)(Ap + k0);
        float4 bv = *(const float4*)(Bp + k0);
        As[lc + 0][lr] = av.x; As[lc + 1][lr] = av.y;
        As[lc + 2][lr] = av.z; As[lc + 3][lr] = av.w;
        Bs[lc + 0][lr] = bv.x; Bs[lc + 1][lr] = bv.y;
        Bs[lc + 2][lr] = bv.z; Bs[lc + 3][lr] = bv.w;
        __syncthreads();
#pragma unroll
        for (int kk = 0; kk < 8; ++kk) {
            float4 a0 = *(const float4*)&As[kk][ty * 8];
            float4 a1 = *(const float4*)&As[kk][ty * 8 + 4];
            float4 b0 = *(const float4*)&Bs[kk][tx * 8];
            float4 b1 = *(const float4*)&Bs[kk][tx * 8 + 4];
            float ar[8] = {a0.x, a0.y, a0.z, a0.w, a1.x, a1.y, a1.z, a1.w};
            float br[8] = {b0.x, b0.y, b0.z, b0.w, b1.x, b1.y, b1.z, b1.w};
#pragma unroll
            for (int i = 0; i < 8; ++i)
#pragma unroll
                for (int j = 0; j < 8; ++j)
                    acc[i][j] += ar[i] * br[j];
        }
        __syncthreads();
    }

#pragma unroll
    for (int i = 0; i < 8; ++i) {
        float* crow = C + (size_t)(rowBase + ty * 8 + i) * N + colBase + tx * 8;
        float4 c0 = {acc[i][0], acc[i][1], acc[i][2], acc[i][3]};
        float4 c1 = {acc[i][4], acc[i][5], acc[i][6], acc[i][7]};
        *(float4*)(crow)     = c0;
        *(float4*)(crow + 4) = c1;
    }
}

// ---------------------------------------------------------------------------
// RoPE + unit-norm + q*attn_scale; splits qkv into [b,h,s,hd] q/k/v buffers.
// One block (64 threads) per (b, s, h) row. Thread i handles pair (2i, 2i+1).
// ---------------------------------------------------------------------------
__global__ __launch_bounds__(64)
void rope_norm_kernel(const float* __restrict__ qkv,
                      const float* __restrict__ freqs,
                      const float* __restrict__ scale_p,
                      float* __restrict__ gq, float* __restrict__ gk,
                      float* __restrict__ gv)
{
    const int idx = blockIdx.x;
    const int h = idx % H_;
    const int s = (idx / H_) % S_;
    const int b = idx / (H_ * S_);
    const int i = threadIdx.x;   // 0..63

    const float* base = qkv + (size_t)(b * S_ + s) * NQKV + h * HD_;
    float q0 = base[2 * i],           q1 = base[2 * i + 1];
    float k0 = base[D_ + 2 * i],      k1 = base[D_ + 2 * i + 1];
    float v0 = base[2 * D_ + 2 * i],  v1 = base[2 * D_ + 2 * i + 1];

    float c  = freqs[((size_t)s * 64 + i) * 2 + 0];
    float sn = freqs[((size_t)s * 64 + i) * 2 + 1];

    float qr = q0 * c - q1 * sn, qi = q0 * sn + q1 * c;
    float kr = k0 * c - k1 * sn, ki = k0 * sn + k1 * c;

    float sq = qr * qr + qi * qi;
    float sk = kr * kr + ki * ki;
#pragma unroll
    for (int off = 16; off > 0; off >>= 1) {
        sq += __shfl_xor_sync(0xffffffffu, sq, off);
        sk += __shfl_xor_sync(0xffffffffu, sk, off);
    }
    __shared__ float smq[2], smk[2];
    if ((i & 31) == 0) { smq[i >> 5] = sq; smk[i >> 5] = sk; }
    __syncthreads();
    float nq = sqrtf(smq[0] + smq[1]) + 1e-6f;
    float nk = sqrtf(smk[0] + smk[1]) + 1e-6f;

    float scl = *scale_p;
    float qs = scl / nq;
    float ks = 1.0f / nk;

    size_t o = ((size_t)(b * H_ + h) * S_ + s) * HD_;
    gq[o + 2 * i] = qr * qs;  gq[o + 2 * i + 1] = qi * qs;
    gk[o + 2 * i] = kr * ks;  gk[o + 2 * i + 1] = ki * ks;
    gv[o + 2 * i] = v0;       gv[o + 2 * i + 1] = v1;
}

// ---------------------------------------------------------------------------
// fp32 flash attention, causal. BM=BN=64, HD=128, 256 threads.
// Smem: QsT[128][68], KsT[128][68] (k-major/transposed), Vs[64][128],
//       PsT[64][68] (col-major P for the PV GEMM).
// Thread grid 16x16; 4x4 S microtile; 4x8 O microtile.
// Output written to g_attn in [b,s,h,hd] layout.
// ---------------------------------------------------------------------------
#define FA_SMEM_FLOATS (128 * 68 + 128 * 68 + 64 * 128 + 64 * 68)
#define FA_SMEM_BYTES  (FA_SMEM_FLOATS * 4)

__global__ __launch_bounds__(256)
void flash_attn(const float* __restrict__ gq, const float* __restrict__ gk,
                const float* __restrict__ gv, float* __restrict__ gout)
{
    extern __shared__ float sm[];
    float* QsT = sm;                    // 128*68
    float* KsT = QsT + 128 * 68;        // 128*68
    float* Vs  = KsT + 128 * 68;        // 64*128
    float* PsT = Vs + 64 * 128;         // 64*68

    const int t  = threadIdx.x;
    const int tx = t & 15;
    const int ty = t >> 4;
    const int qt = blockIdx.x;          // q tile (0..31)
    const int bh = blockIdx.y;          // 0..31
    const int b  = bh >> 4;
    const int h  = bh & 15;

    const float* Qg = gq + ((size_t)bh * S_ + qt * 64) * HD_;
    const float* Kg = gk + (size_t)bh * S_ * HD_;
    const float* Vg = gv + (size_t)bh * S_ * HD_;

    // Load Q tile transposed (QsT[d][r])
    {
        const int r = t >> 2, db = (t & 3) << 2;
        const float* src = Qg + (size_t)r * HD_;
#pragma unroll
        for (int it = 0; it < 8; ++it) {
            int d = db + it * 16;
            float4 v = *(const float4*)(src + d);
            QsT[(d + 0) * 68 + r] = v.x;
            QsT[(d + 1) * 68 + r] = v.y;
            QsT[(d + 2) * 68 + r] = v.z;
            QsT[(d + 3) * 68 + r] = v.w;
        }
    }

    float O[4][8];
    float m[4], l[4];
#pragma unroll
    for (int i = 0; i < 4; ++i) {
        m[i] = -1e30f; l[i] = 0.f;
#pragma unroll
        for (int j = 0; j < 8; ++j) O[i][j] = 0.f;
    }

    for (int kt = 0; kt <= qt; ++kt) {
        __syncthreads();   // previous iteration's PV reads done (also Q load, 1st iter)
        // Load K tile transposed + V tile
        {
            const int r = t >> 2, db = (t & 3) << 2;
            const float* ksrc = Kg + (size_t)(kt * 64 + r) * HD_;
            const float* vsrc = Vg + (size_t)(kt * 64 + r) * HD_;
#pragma unroll
            for (int it = 0; it < 8; ++it) {
                int d = db + it * 16;
                float4 kv = *(const float4*)(ksrc + d);
                KsT[(d + 0) * 68 + r] = kv.x;
                KsT[(d + 1) * 68 + r] = kv.y;
                KsT[(d + 2) * 68 + r] = kv.z;
                KsT[(d + 3) * 68 + r] = kv.w;
                *(float4*)&Vs[r * 128 + d] = *(const float4*)(vsrc + d);
            }
        }
        __syncthreads();

        // S = Q K^T  (per-thread 4x4)
        float sc[4][4];
#pragma unroll
        for (int i = 0; i < 4; ++i)
#pragma unroll
            for (int j = 0; j < 4; ++j) sc[i][j] = 0.f;

#pragma unroll 8
        for (int d = 0; d < 128; ++d) {
            float4 qa = *(const float4*)&QsT[d * 68 + ty * 4];
            float4 ka = *(const float4*)&KsT[d * 68 + tx * 4];
            float ar[4] = {qa.x, qa.y, qa.z, qa.w};
            float br[4] = {ka.x, ka.y, ka.z, ka.w};
#pragma unroll
            for (int i = 0; i < 4; ++i)
#pragma unroll
                for (int j = 0; j < 4; ++j)
                    sc[i][j] += ar[i] * br[j];
        }

        if (kt == qt) {  // causal mask on the diagonal tile
#pragma unroll
            for (int i = 0; i < 4; ++i)
#pragma unroll
                for (int j = 0; j < 4; ++j)
                    if (tx * 4 + j > ty * 4 + i) sc[i][j] = -1e30f;
        }

        // Online softmax (row stats across the 16-lane tx group)
#pragma unroll
        for (int i = 0; i < 4; ++i) {
            float rm = fmaxf(fmaxf(sc[i][0], sc[i][1]), fmaxf(sc[i][2], sc[i][3]));
#pragma unroll
            for (int off = 8; off > 0; off >>= 1)
                rm = fmaxf(rm, __shfl_xor_sync(0xffffffffu, rm, off));
            float mn = fmaxf(m[i], rm);
            float alpha = __expf(m[i] - mn);
            float rs = 0.f;
#pragma unroll
            for (int j = 0; j < 4; ++j) {
                float p = __expf(sc[i][j] - mn);
                sc[i][j] = p;
                rs += p;
            }
#pragma unroll
            for (int off = 8; off > 0; off >>= 1)
                rs += __shfl_xor_sync(0xffffffffu, rs, off);
            l[i] = l[i] * alpha + rs;
            m[i] = mn;
#pragma unroll
            for (int j = 0; j < 8; ++j) O[i][j] *= alpha;
        }

        // Store P transposed: PsT[col][row]
#pragma unroll
        for (int i = 0; i < 4; ++i)
#pragma unroll
            for (int j = 0; j < 4; ++j)
                PsT[(tx * 4 + j) * 68 + ty * 4 + i] = sc[i][j];
        __syncthreads();

        // O += P @ V
#pragma unroll 4
        for (int k = 0; k < 64; ++k) {
            float4 pa = *(const float4*)&PsT[k * 68 + ty * 4];
            float pr[4] = {pa.x, pa.y, pa.z, pa.w};
            float4 v0 = *(const float4*)&Vs[k * 128 + tx * 8];
            float4 v1 = *(const float4*)&Vs[k * 128 + tx * 8 + 4];
            float vr[8] = {v0.x, v0.y, v0.z, v0.w, v1.x, v1.y, v1.z, v1.w};
#pragma unroll
            for (int i = 0; i < 4; ++i)
#pragma unroll
                for (int j = 0; j < 8; ++j)
                    O[i][j] += pr[i] * vr[j];
        }
    }

    // Epilogue: O / l -> g_attn [b,s,h,hd]
#pragma unroll
    for (int i = 0; i < 4; ++i) {
        float inv = 1.f / l[i];
        int qg = qt * 64 + ty * 4 + i;
        float* dst = gout + ((size_t)(b * S_ + qg) * H_ + h) * HD_ + tx * 8;
        float4 o0 = {O[i][0] * inv, O[i][1] * inv, O[i][2] * inv, O[i][3] * inv};
        float4 o1 = {O[i][4] * inv, O[i][5] * inv, O[i][6] * inv, O[i][7] * inv};
        *(float4*)(dst)     = o0;
        *(float4*)(dst + 4) = o1;
    }
}

// ---------------------------------------------------------------------------
extern "C" void kernel_launch(void* const* d_in, const int* in_sizes, int n_in,
                              void* d_out, int out_size)
{
    const float* x      = (const float*)d_in[0];
    const float* freqs  = (const float*)d_in[1];
    const float* wqkv   = (const float*)d_in[2];
    const float* wout   = (const float*)d_in[3];
    const float* ascale = (const float*)d_in[4];
    float* out = (float*)d_out;

    float *qkv, *q, *k, *v, *attn;
    cudaGetSymbolAddress((void**)&qkv,  g_qkv);
    cudaGetSymbolAddress((void**)&q,    g_q);
    cudaGetSymbolAddress((void**)&k,    g_k);
    cudaGetSymbolAddress((void**)&v,    g_v);
    cudaGetSymbolAddress((void**)&attn, g_attn);

    cudaFuncSetAttribute(flash_attn, cudaFuncAttributeMaxDynamicSharedMemorySize,
                         FA_SMEM_BYTES);

    // 1) qkv = x @ w_qkv^T
    sgemm_nt<<<dim3(NQKV / 128, M_ / 128), 256>>>(x, wqkv, qkv, M_, NQKV, D_);

    // 2) RoPE + norm + scale, split to q/k/v [b,h,s,hd]
    rope_norm_kernel<<<B_ * S_ * H_, 64>>>(qkv, freqs, ascale, q, k, v);

    // 3) causal flash attention -> g_attn [b,s,h,hd]
    flash_attn<<<dim3(S_ / 64, B_ * H_), 256, FA_SMEM_BYTES>>>(q, k, v, attn);

    // 4) out = attn @ w_out^T
    sgemm_nt<<<dim3(D_ / 128, M_ / 128), 256>>>(attn, wout, out, M_, D_, D_);
}